// round 16
// baseline (speedup 1.0000x reference)
#include <cuda_runtime.h>
#include <math.h>

#define NB      2
#define CIN     64
#define HAX     56
#define WAX     56
#define BATCH   112
#define OUTC    64
#define CHUNK   25
#define PADLEN  19
#define EPS_N   5e-5f
#define SROW    84            // 3 segs * 28 (25 valid + 3 pad)

// -------------------- scratch --------------------
__device__ float g_wmatch[BATCH*56*32];
__device__ float g_vmatch[BATCH*56*64];
__device__ int   g_indices[BATCH*224];
__device__ int   g_undo   [BATCH*224];
__device__ float g_ret1[BATCH*38400];         // (b, g,h2,k,i,e16)
__device__ float g_bsg [BATCH*8*4*75];        // (b, g, h2, t75)
__device__ float g_psum[BATCH*2400];          // (b, cq8, p)

// -------------------- kernel 1a: conv1x1 + BN + reshape-scatter --------------------
__global__ __launch_bounds__(256)
void k_conv(const float* __restrict__ x, const float* __restrict__ cw,
            const float* __restrict__ gamma, const float* __restrict__ beta)
{
    __shared__ float xs[CIN*HAX];
    __shared__ float wst[CIN*24];
    __shared__ float gb[48];
    int b = blockIdx.x, q = blockIdx.y;
    int n = b / WAX, w = b % WAX;
    int tid = threadIdx.x;

    for (int i = tid; i < CIN*HAX; i += 256) {
        int c = i / HAX, h = i % HAX;
        xs[i] = x[((n*CIN + c)*HAX + h)*WAX + w];
    }
    for (int i = tid; i < 24*CIN; i += 256) {
        int oo = i / CIN, c = i % CIN;
        wst[c*24 + oo] = cw[(24*q + oo)*CIN + c];
    }
    if (tid < 24) { gb[tid] = gamma[24*q + tid]; gb[24 + tid] = beta[24*q + tid]; }
    __syncthreads();

    const float inv = rsqrtf(1.0f + 1e-5f);
    for (int u = tid; u < 6*HAX; u += 256) {
        int o4 = u / HAX, h = u % HAX;
        float4 acc = make_float4(0.f, 0.f, 0.f, 0.f);
        #pragma unroll 16
        for (int c = 0; c < CIN; c++) {
            float xv = xs[c*HAX + h];
            float4 w4 = *reinterpret_cast<const float4*>(&wst[c*24 + 4*o4]);
            acc.x += xv*w4.x; acc.y += xv*w4.y; acc.z += xv*w4.z; acc.w += xv*w4.w;
        }
        float av[4] = {acc.x, acc.y, acc.z, acc.w};
        #pragma unroll
        for (int oo = 0; oo < 4; oo++) {
            int ol = 4*o4 + oo;
            int o  = 24*q + ol;
            float v = av[oo]*inv*gb[ol] + gb[24 + ol];
            int flat = o*HAX + h, t = flat / 96, f = flat % 96;
            if (f < 32) g_wmatch[(b*56 + t)*32 + f]        = v;
            else        g_vmatch[(b*56 + t)*64 + (f - 32)] = v;
        }
    }
}

// -------------------- kernel 1b: hash codes + stable rank sort --------------------
__global__ __launch_bounds__(224)
void k_code(const float* __restrict__ rot)
{
    __shared__ int cd[224];
    int b = blockIdx.x, tid = threadIdx.x;
    int hh = tid / 56, t = tid % 56;
    const float* wrow = &g_wmatch[(b*56 + t)*32];
    float acc = 0.f;
    #pragma unroll
    for (int f = 0; f < 32; f++) acc += wrow[f] * rot[f*4 + hh];
    cd[tid] = ((acc < 0.0f) ? 1 : 0) + 2*hh;
    __syncthreads();

    int c = cd[tid], rank = 0;
    for (int qq = 0; qq < 224; qq++) {
        int cq = cd[qq];
        rank += (cq < c) || (cq == c && qq < tid);
    }
    g_indices[b*224 + rank] = tid;
    g_undo   [b*224 + tid]  = rank;
}

// -------------------- kernel 2: fused chunked attention (split-k) --------------------
struct SmemAtt {
    float w_t[8][25][4];       // raw query rows (chunk k only)
    float w_n[8][3][25][4];    // normalized key rows
    float v_t[8][3][25][8];
    float we [3][25][4];
    float ve [3][25][8];
    float s  [8][25][SROW];    // scores: unnormalized (phase1) -> probs (phase2)
    float rdn[25][SROW];       // cross-group 1/norm per (i,j)
};

__global__ __launch_bounds__(512, 2)
void k_attn(const float* __restrict__ relative)
{
    extern __shared__ char smraw[];
    SmemAtt* sm = reinterpret_cast<SmemAtt*>(smraw);
    const int b = blockIdx.x, h2 = blockIdx.y, k = blockIdx.z;
    const int kp = (k + 2) % 3, kn = (k + 1) % 3;
    const int tid = threadIdx.x;

    // ---- gather tiles ----
    for (int idx = tid; idx < 8*75; idx += 512) {
        int g = idx / 75, rem = idx % 75;
        int kk = rem / 25, i = rem % 25;
        int tc  = (g & 1)*300 + h2*75 + rem;
        int hp  = g >> 1;
        int tp  = tc >> 3, c = tc & 7;
        int t56 = (tp < 56) ? tp : tp - PADLEN;
        int src = g_indices[b*224 + hp*56 + t56] % 56;
        float4 wv = *reinterpret_cast<const float4*>(&g_wmatch[(b*56 + src)*32 + 4*c]);
        if (kk == k) *reinterpret_cast<float4*>(sm->w_t[g][i]) = wv;
        float nn = wv.x*wv.x + wv.y*wv.y + wv.z*wv.z + wv.w*wv.w;
        float in = 1.0f / fmaxf(sqrtf(nn), EPS_N);
        float4 wn; wn.x = wv.x*in; wn.y = wv.y*in; wn.z = wv.z*in; wn.w = wv.w*in;
        *reinterpret_cast<float4*>(sm->w_n[g][kk][i]) = wn;
        const float4* vp = reinterpret_cast<const float4*>(&g_vmatch[(b*56 + src)*64 + 8*c]);
        *reinterpret_cast<float4*>(&sm->v_t[g][kk][i][0]) = vp[0];
        *reinterpret_cast<float4*>(&sm->v_t[g][kk][i][4]) = vp[1];
    }
    for (int idx = tid; idx < 75; idx += 512) {
        int kk = idx / 25, i = idx % 25;
        int t56 = (idx < 56) ? idx : idx - PADLEN;
        const float* rr = &relative[t56*12];
        #pragma unroll
        for (int e = 0; e < 4; e++) sm->we[kk][i][e] = rr[e];
        #pragma unroll
        for (int e = 0; e < 8; e++) sm->ve[kk][i][e] = rr[4 + e];
    }
    __syncthreads();

    // ---- phase 1: scores (unnormalized) + rdn, float4 conflict-free stores ----
    for (int u = tid; u < 525; u += 512) {
        int row = u % 25, sb = u / 25;       // sb = seg*7 + blk; lanes row-consecutive
        int seg = sb / 7, blk = sb % 7;
        int kk = (seg == 0) ? k : ((seg == 1) ? kp : kn);
        int j0 = blk * 4;
        float4 wev[4];
        #pragma unroll
        for (int e = 0; e < 4; e++) {
            int jjc = (j0 + e < 25) ? (j0 + e) : 24;
            wev[e] = *reinterpret_cast<const float4*>(sm->we[kk][jjc]);
        }
        float ssq[4] = {0.f, 0.f, 0.f, 0.f};
        #pragma unroll
        for (int g = 0; g < 8; g++) {
            float4 a = *reinterpret_cast<const float4*>(sm->w_t[g][row]);
            float vr[4];
            #pragma unroll
            for (int e = 0; e < 4; e++) {
                int jjc = (j0 + e < 25) ? (j0 + e) : 24;
                float4 mn = *reinterpret_cast<const float4*>(sm->w_n[g][kk][jjc]);
                float raw = a.x*mn.x + a.y*mn.y + a.z*mn.z + a.w*mn.w;
                float emb = 0.1f*(a.x*wev[e].x + a.y*wev[e].y + a.z*wev[e].z + a.w*wev[e].w);
                vr[e] = raw + emb;
                ssq[e] += raw*raw + emb*emb;
            }
            float4 vv;
            vv.x = vr[0]; vv.y = vr[1]; vv.z = vr[2]; vv.w = vr[3];
            if (blk == 6) { vv.y = -1e30f; vv.z = -1e30f; vv.w = -1e30f; }
            *reinterpret_cast<float4*>(&sm->s[g][row][sb*4]) = vv;
        }
        float4 rv;
        rv.x = 1.0f / fmaxf(sqrtf(ssq[0]), EPS_N);
        rv.y = 1.0f / fmaxf(sqrtf(ssq[1]), EPS_N);
        rv.z = 1.0f / fmaxf(sqrtf(ssq[2]), EPS_N);
        rv.w = 1.0f / fmaxf(sqrtf(ssq[3]), EPS_N);
        *reinterpret_cast<float4*>(&sm->rdn[row][sb*4]) = rv;
    }
    __syncthreads();

    // ---- phase 2: apply rdn + logsumexp per (g,i) row ----
    {
        int warp = tid >> 5, lane = tid & 31;
        for (int rowi = warp; rowi < 200; rowi += 16) {
            int g = rowi / 25, i = rowi % 25;
            float* r = sm->s[g][i];
            float4 v4 = make_float4(-1e30f, -1e30f, -1e30f, -1e30f);
            if (lane < 21) {
                v4 = *reinterpret_cast<const float4*>(&r[4*lane]);
                float4 rd4 = *reinterpret_cast<const float4*>(&sm->rdn[i][4*lane]);
                v4.x *= rd4.x; v4.y *= rd4.y; v4.z *= rd4.z; v4.w *= rd4.w;
            }
            float m = fmaxf(fmaxf(v4.x, v4.y), fmaxf(v4.z, v4.w));
            #pragma unroll
            for (int o = 16; o; o >>= 1) m = fmaxf(m, __shfl_xor_sync(~0u, m, o));
            float4 e4 = make_float4(0.f,0.f,0.f,0.f);
            float sum = 0.f;
            if (lane < 21) {
                e4.x = __expf(v4.x - m); e4.y = __expf(v4.y - m);
                e4.z = __expf(v4.z - m); e4.w = __expf(v4.w - m);
                sum = e4.x + e4.y + e4.z + e4.w;
            }
            #pragma unroll
            for (int o = 16; o; o >>= 1) sum += __shfl_xor_sync(~0u, sum, o);
            float rs = 1.0f / sum;
            if (lane < 21) {
                e4.x *= rs; e4.y *= rs; e4.z *= rs; e4.w *= rs;
                *reinterpret_cast<float4*>(&r[4*lane]) = e4;
            }
            if (lane == 0)
                g_bsg[((b*8 + g)*4 + h2)*75 + k*25 + i] = m + __logf(sum);
        }
    }
    __syncthreads();

    // ---- phase 3: score @ V, stride-7 row tiling (bank-conflict-free score loads) ----
    if (tid < 224) {
        int g  = tid / 28, rem = tid % 28;
        int iq = rem / 4,  q   = rem % 4;
        int i0 = iq, i1 = iq + 7, i2 = iq + 14;
        bool has3 = (iq + 21) < 25;
        int i3 = has3 ? iq + 21 : 24;
        float4 ac0 = make_float4(0.f,0.f,0.f,0.f);
        float4 ac1 = make_float4(0.f,0.f,0.f,0.f);
        float4 ac2 = make_float4(0.f,0.f,0.f,0.f);
        float4 ac3 = make_float4(0.f,0.f,0.f,0.f);
        int korder[3] = {k, kp, kn};
        #pragma unroll
        for (int seg = 0; seg < 3; seg++) {
            int kk = korder[seg];
            const float4* vp = (q < 2)
                ? reinterpret_cast<const float4*>(&sm->v_t[g][kk][0][4*q])
                : reinterpret_cast<const float4*>(&sm->ve[kk][0][4*(q-2)]);
            const float* sb0 = &sm->s[g][i0][seg*28];
            const float* sb1 = &sm->s[g][i1][seg*28];
            const float* sb2 = &sm->s[g][i2][seg*28];
            const float* sb3 = &sm->s[g][i3][seg*28];
            #pragma unroll
            for (int j4 = 0; j4 < 6; j4++) {
                float4 s0 = *reinterpret_cast<const float4*>(&sb0[4*j4]);
                float4 s1 = *reinterpret_cast<const float4*>(&sb1[4*j4]);
                float4 s2 = *reinterpret_cast<const float4*>(&sb2[4*j4]);
                float4 s3 = *reinterpret_cast<const float4*>(&sb3[4*j4]);
                const float sa0[4] = {s0.x, s0.y, s0.z, s0.w};
                const float sa1[4] = {s1.x, s1.y, s1.z, s1.w};
                const float sa2[4] = {s2.x, s2.y, s2.z, s2.w};
                const float sa3[4] = {s3.x, s3.y, s3.z, s3.w};
                #pragma unroll
                for (int e = 0; e < 4; e++) {
                    float4 v = vp[2*(4*j4 + e)];
                    float a0 = sa0[e];
                    ac0.x += a0*v.x; ac0.y += a0*v.y; ac0.z += a0*v.z; ac0.w += a0*v.w;
                    float a1 = sa1[e];
                    ac1.x += a1*v.x; ac1.y += a1*v.y; ac1.z += a1*v.z; ac1.w += a1*v.w;
                    float a2 = sa2[e];
                    ac2.x += a2*v.x; ac2.y += a2*v.y; ac2.z += a2*v.z; ac2.w += a2*v.w;
                    float a3 = sa3[e];
                    ac3.x += a3*v.x; ac3.y += a3*v.y; ac3.z += a3*v.z; ac3.w += a3*v.w;
                }
            }
            {   // tail j = 24
                float4 v = vp[48];
                float a0 = sb0[24];
                ac0.x += a0*v.x; ac0.y += a0*v.y; ac0.z += a0*v.z; ac0.w += a0*v.w;
                float a1 = sb1[24];
                ac1.x += a1*v.x; ac1.y += a1*v.y; ac1.z += a1*v.z; ac1.w += a1*v.w;
                float a2 = sb2[24];
                ac2.x += a2*v.x; ac2.y += a2*v.y; ac2.z += a2*v.z; ac2.w += a2*v.w;
                float a3 = sb3[24];
                ac3.x += a3*v.x; ac3.y += a3*v.y; ac3.z += a3*v.z; ac3.w += a3*v.w;
            }
        }
        if (q >= 2) {
            ac0.x *= 0.1f; ac0.y *= 0.1f; ac0.z *= 0.1f; ac0.w *= 0.1f;
            ac1.x *= 0.1f; ac1.y *= 0.1f; ac1.z *= 0.1f; ac1.w *= 0.1f;
            ac2.x *= 0.1f; ac2.y *= 0.1f; ac2.z *= 0.1f; ac2.w *= 0.1f;
            ac3.x *= 0.1f; ac3.y *= 0.1f; ac3.z *= 0.1f; ac3.w *= 0.1f;
        }
        int base_out = b*38400 + g*4800 + h2*1200 + k*400 + 4*q;
        *reinterpret_cast<float4*>(&g_ret1[base_out + i0*16]) = ac0;
        *reinterpret_cast<float4*>(&g_ret1[base_out + i1*16]) = ac1;
        *reinterpret_cast<float4*>(&g_ret1[base_out + i2*16]) = ac2;
        if (has3)
            *reinterpret_cast<float4*>(&g_ret1[base_out + i3*16]) = ac3;
    }
}

// -------------------- kernel 3a: partial sum-of-squares (8-way split) -------------
__global__ __launch_bounds__(320)
void k_psum()
{
    int b = blockIdx.x, cq = blockIdx.y, tid = threadIdx.x;
    if (tid >= 300) return;
    const float* rb = &g_ret1[b*38400];
    float ss = 0.f;
    #pragma unroll
    for (int cc = 0; cc < 16; cc++) {
        float v = rb[(cq*16 + cc)*300 + tid];
        ss += v*v;
    }
    g_psum[b*2400 + cq*300 + tid] = ss;
}

// -------------------- kernel 3b: norms + undo-gather + hash softmax + store ------
__global__ __launch_bounds__(512)
void k_fin(float* __restrict__ out)
{
    __shared__ float rd[300];
    __shared__ float bsn[224];
    __shared__ int   u[224];
    __shared__ float prob[4][28];
    int b = blockIdx.x, th = blockIdx.y;
    int n = b / WAX, w = b % WAX;
    int tid = threadIdx.x;
    const float* rb = &g_ret1[b*38400];
    const int t0 = th*28;

    if (tid < 300) {
        const float* pp = &g_psum[b*2400];
        float s = 0.f;
        #pragma unroll
        for (int c = 0; c < 8; c++) s += pp[c*300 + tid];
        rd[tid] = 1.0f / fmaxf(sqrtf(s), EPS_N);
    }
    if (tid >= 288) {
        int p = tid - 288;
        int h2 = p / 56, t = p % 56;
        float sv = 0.f, sq = 0.f;
        #pragma unroll
        for (int g = 0; g < 8; g++) {
            float v = g_bsg[((b*8 + g)*4 + h2)*75 + t];
            sv += v; sq += v*v;
        }
        bsn[p] = sv / fmaxf(sqrtf(sq), EPS_N);
        u[p] = g_undo[b*224 + p];
    }
    __syncthreads();

    if (tid < 28) {
        int t = t0 + tid;
        float bv[4]; float m = -1e30f;
        #pragma unroll
        for (int h = 0; h < 4; h++) { bv[h] = bsn[u[h*56 + t]]; m = fmaxf(m, bv[h]); }
        float sum = 0.f;
        #pragma unroll
        for (int h = 0; h < 4; h++) { float e = __expf(bv[h] - m); prob[h][tid] = e; sum += e; }
        float rs = 1.0f / sum;
        #pragma unroll
        for (int h = 0; h < 4; h++) prob[h][tid] *= rs;
    }
    __syncthreads();

    for (int o = tid; o < 28*32; o += 512) {
        int tl = o >> 5, e2 = o & 31;
        int t  = t0 + tl;
        float acc0 = 0.f, acc1 = 0.f;
        #pragma unroll
        for (int h = 0; h < 4; h++) {
            int p  = u[h*56 + t];
            int h4 = p / 56, t2 = p % 56, k4 = t2 / 25, i4 = t2 % 25;
            int f0 = h4*9600 + k4*3200 + i4*128 + 4*e2;
            float4 rv = *reinterpret_cast<const float4*>(&rb[f0]);
            int m0 = (200*k4 + 128*i4 + 4*e2) % 300;
            int m2 = m0 + 2; if (m2 >= 300) m2 -= 300;
            float ph = prob[h][tl];
            acc0 += (rv.x*rd[m0] + rv.y*rd[m0+1]) * ph;
            acc1 += (rv.z*rd[m2] + rv.w*rd[m2+1]) * ph;
        }
        int e = 2*e2;
        out[((n*OUTC + e    )*HAX + t)*WAX + w] = acc0;
        out[((n*OUTC + e + 1)*HAX + t)*WAX + w] = acc1;
    }
}

// -------------------- launch --------------------
extern "C" void kernel_launch(void* const* d_in, const int* in_sizes, int n_in,
                              void* d_out, int out_size)
{
    const float* x     = (const float*)d_in[0];
    const float* cw    = (const float*)d_in[1];
    const float* gamma = (const float*)d_in[2];
    const float* beta  = (const float*)d_in[3];
    const float* rel   = (const float*)d_in[4];
    const float* rot   = (const float*)d_in[5];
    float* out = (float*)d_out;

    cudaFuncSetAttribute(k_attn, cudaFuncAttributeMaxDynamicSharedMemorySize,
                         (int)sizeof(SmemAtt));

    k_conv<<<dim3(BATCH, 4), 256>>>(x, cw, gamma, beta);
    k_code<<<BATCH, 224>>>(rot);
    k_attn<<<dim3(BATCH, 4, 3), 512, sizeof(SmemAtt)>>>(rel);
    k_psum<<<dim3(BATCH, 8), 320>>>();
    k_fin <<<dim3(BATCH, 2), 512>>>(out);
}

// round 17
// speedup vs baseline: 1.0153x; 1.0153x over previous
#include <cuda_runtime.h>
#include <math.h>

#define NB      2
#define CIN     64
#define HAX     56
#define WAX     56
#define BATCH   112
#define OUTC    64
#define CHUNK   25
#define PADLEN  19
#define EPS_N   5e-5f
#define SROW    84            // 3 segs * 28 (25 valid + 3 pad)

// -------------------- scratch --------------------
__device__ float g_wmatch[BATCH*56*32];
__device__ float g_vmatch[BATCH*56*64];
__device__ int   g_indices[BATCH*224];
__device__ int   g_undo   [BATCH*224];
__device__ float g_ret1[BATCH*38400];         // (b, g,h2,k,i,e16)
__device__ float g_bsg [BATCH*8*4*75];        // (b, g, h2, t75)
__device__ float g_pp  [BATCH*12*400];        // (b, h2*3+k, 16i+e) sq-partials (sum over g)

// -------------------- kernel 1a: conv1x1 + BN + reshape-scatter --------------------
__global__ __launch_bounds__(256)
void k_conv(const float* __restrict__ x, const float* __restrict__ cw,
            const float* __restrict__ gamma, const float* __restrict__ beta)
{
    __shared__ float xs[CIN*HAX];
    __shared__ float wst[CIN*24];
    __shared__ float gb[48];
    int b = blockIdx.x, q = blockIdx.y;
    int n = b / WAX, w = b % WAX;
    int tid = threadIdx.x;

    for (int i = tid; i < CIN*HAX; i += 256) {
        int c = i / HAX, h = i % HAX;
        xs[i] = x[((n*CIN + c)*HAX + h)*WAX + w];
    }
    for (int i = tid; i < 24*CIN; i += 256) {
        int oo = i / CIN, c = i % CIN;
        wst[c*24 + oo] = cw[(24*q + oo)*CIN + c];
    }
    if (tid < 24) { gb[tid] = gamma[24*q + tid]; gb[24 + tid] = beta[24*q + tid]; }
    __syncthreads();

    const float inv = rsqrtf(1.0f + 1e-5f);
    for (int u = tid; u < 6*HAX; u += 256) {
        int o4 = u / HAX, h = u % HAX;
        float4 acc = make_float4(0.f, 0.f, 0.f, 0.f);
        #pragma unroll 16
        for (int c = 0; c < CIN; c++) {
            float xv = xs[c*HAX + h];
            float4 w4 = *reinterpret_cast<const float4*>(&wst[c*24 + 4*o4]);
            acc.x += xv*w4.x; acc.y += xv*w4.y; acc.z += xv*w4.z; acc.w += xv*w4.w;
        }
        float av[4] = {acc.x, acc.y, acc.z, acc.w};
        #pragma unroll
        for (int oo = 0; oo < 4; oo++) {
            int ol = 4*o4 + oo;
            int o  = 24*q + ol;
            float v = av[oo]*inv*gb[ol] + gb[24 + ol];
            int flat = o*HAX + h, t = flat / 96, f = flat % 96;
            if (f < 32) g_wmatch[(b*56 + t)*32 + f]        = v;
            else        g_vmatch[(b*56 + t)*64 + (f - 32)] = v;
        }
    }
}

// -------------------- kernel 1b: hash codes + stable rank sort --------------------
__global__ __launch_bounds__(224)
void k_code(const float* __restrict__ rot)
{
    __shared__ int cd[224];
    int b = blockIdx.x, tid = threadIdx.x;
    int hh = tid / 56, t = tid % 56;
    const float* wrow = &g_wmatch[(b*56 + t)*32];
    float acc = 0.f;
    #pragma unroll
    for (int f = 0; f < 32; f++) acc += wrow[f] * rot[f*4 + hh];
    cd[tid] = ((acc < 0.0f) ? 1 : 0) + 2*hh;
    __syncthreads();

    int c = cd[tid], rank = 0;
    for (int qq = 0; qq < 224; qq++) {
        int cq = cd[qq];
        rank += (cq < c) || (cq == c && qq < tid);
    }
    g_indices[b*224 + rank] = tid;
    g_undo   [b*224 + tid]  = rank;
}

// -------------------- kernel 2: fused chunked attention (split-k) --------------------
struct SmemAtt {
    float w_t[8][25][4];       // raw query rows (phase 1 only; reused as sq buffer)
    float w_n[8][3][25][4];    // normalized key rows (phase 1 only; reused as sq buffer)
    float v_t[8][3][25][8];
    float we [3][25][4];
    float ve [3][25][8];
    float s  [8][25][SROW];    // fp32 scores, seg-padded (3 x 28)
};

__global__ __launch_bounds__(512, 2)
void k_attn(const float* __restrict__ relative)
{
    extern __shared__ char smraw[];
    SmemAtt* sm = reinterpret_cast<SmemAtt*>(smraw);
    const int b = blockIdx.x, h2 = blockIdx.y, k = blockIdx.z;
    const int kp = (k + 2) % 3, kn = (k + 1) % 3;
    const int tid = threadIdx.x;

    // ---- gather tiles + pad init ----
    for (int idx = tid; idx < 8*75; idx += 512) {
        int g = idx / 75, rem = idx % 75;
        int kk = rem / 25, i = rem % 25;
        int tc  = (g & 1)*300 + h2*75 + rem;
        int hp  = g >> 1;
        int tp  = tc >> 3, c = tc & 7;
        int t56 = (tp < 56) ? tp : tp - PADLEN;
        int src = g_indices[b*224 + hp*56 + t56] % 56;
        float4 wv = *reinterpret_cast<const float4*>(&g_wmatch[(b*56 + src)*32 + 4*c]);
        if (kk == k) *reinterpret_cast<float4*>(sm->w_t[g][i]) = wv;
        float nn = wv.x*wv.x + wv.y*wv.y + wv.z*wv.z + wv.w*wv.w;
        float in = 1.0f / fmaxf(sqrtf(nn), EPS_N);
        float4 wn; wn.x = wv.x*in; wn.y = wv.y*in; wn.z = wv.z*in; wn.w = wv.w*in;
        *reinterpret_cast<float4*>(sm->w_n[g][kk][i]) = wn;
        const float4* vp = reinterpret_cast<const float4*>(&g_vmatch[(b*56 + src)*64 + 8*c]);
        *reinterpret_cast<float4*>(&sm->v_t[g][kk][i][0]) = vp[0];
        *reinterpret_cast<float4*>(&sm->v_t[g][kk][i][4]) = vp[1];
        float* pd = &sm->s[g][i][kk*28 + 25];
        pd[0] = -1e30f; pd[1] = -1e30f; pd[2] = -1e30f;
    }
    for (int idx = tid; idx < 75; idx += 512) {
        int kk = idx / 25, i = idx % 25;
        int t56 = (idx < 56) ? idx : idx - PADLEN;
        const float* rr = &relative[t56*12];
        #pragma unroll
        for (int e = 0; e < 4; e++) sm->we[kk][i][e] = rr[e];
        #pragma unroll
        for (int e = 0; e < 8; e++) sm->ve[kk][i][e] = rr[4 + e];
    }
    __syncthreads();

    // ---- phase 1: scores + cross-group L2 norm (lane = row: broadcast key loads) ----
    if (tid < 500) {
        int row = tid % 25, col = tid / 25;
        float4 a[8];
        #pragma unroll
        for (int g = 0; g < 8; g++) a[g] = *reinterpret_cast<const float4*>(sm->w_t[g][row]);
        #pragma unroll
        for (int jj4 = 0; jj4 < 4; jj4++) {
            int j = col*4 + jj4;
            if (j < 75) {
                int kk, seg, jj;
                if (j < 25)      { kk = k;  seg = 0; jj = j;      }
                else if (j < 50) { kk = kp; seg = 1; jj = j - 25; }
                else             { kk = kn; seg = 2; jj = j - 50; }
                float4 we4 = *reinterpret_cast<const float4*>(sm->we[kk][jj]);
                float vals[8]; float ssq = 0.f;
                #pragma unroll
                for (int g = 0; g < 8; g++) {
                    float4 mn = *reinterpret_cast<const float4*>(sm->w_n[g][kk][jj]);
                    float raw = a[g].x*mn.x + a[g].y*mn.y + a[g].z*mn.z + a[g].w*mn.w;
                    float emb = 0.1f*(a[g].x*we4.x + a[g].y*we4.y + a[g].z*we4.z + a[g].w*we4.w);
                    vals[g] = raw + emb;
                    ssq += raw*raw + emb*emb;
                }
                float rdv = 1.0f / fmaxf(sqrtf(ssq), EPS_N);
                int soff = seg*28 + jj;
                #pragma unroll
                for (int g = 0; g < 8; g++) sm->s[g][row][soff] = vals[g]*rdv;
            }
        }
    }
    __syncthreads();

    // ---- phase 2: vectorized logsumexp per (g,i) row ----
    {
        int warp = tid >> 5, lane = tid & 31;
        for (int rowi = warp; rowi < 200; rowi += 16) {
            int g = rowi / 25, i = rowi % 25;
            float* r = sm->s[g][i];
            float4 v4 = make_float4(-1e30f, -1e30f, -1e30f, -1e30f);
            if (lane < 21) v4 = *reinterpret_cast<const float4*>(&r[4*lane]);
            float m = fmaxf(fmaxf(v4.x, v4.y), fmaxf(v4.z, v4.w));
            #pragma unroll
            for (int o = 16; o; o >>= 1) m = fmaxf(m, __shfl_xor_sync(~0u, m, o));
            float4 e4 = make_float4(0.f,0.f,0.f,0.f);
            float sum = 0.f;
            if (lane < 21) {
                e4.x = __expf(v4.x - m); e4.y = __expf(v4.y - m);
                e4.z = __expf(v4.z - m); e4.w = __expf(v4.w - m);
                sum = e4.x + e4.y + e4.z + e4.w;
            }
            #pragma unroll
            for (int o = 16; o; o >>= 1) sum += __shfl_xor_sync(~0u, sum, o);
            float rs = 1.0f / sum;
            if (lane < 21) {
                e4.x *= rs; e4.y *= rs; e4.z *= rs; e4.w *= rs;
                *reinterpret_cast<float4*>(&r[4*lane]) = e4;
            }
            if (lane == 0)
                g_bsg[((b*8 + g)*4 + h2)*75 + k*25 + i] = m + __logf(sum);
        }
    }
    __syncthreads();

    // sq buffer overlays the (now dead) w_t + w_n region: 3200 floats = [8][400]
    float* sq = &sm->w_t[0][0][0];

    // ---- phase 3: score @ V, stride-7 row tiling + sq-partial stores ----
    if (tid < 224) {
        int g  = tid / 28, rem = tid % 28;
        int iq = rem / 4,  q   = rem % 4;
        int i0 = iq, i1 = iq + 7, i2 = iq + 14;
        bool has3 = (iq + 21) < 25;
        int i3 = has3 ? iq + 21 : 24;
        float4 ac0 = make_float4(0.f,0.f,0.f,0.f);
        float4 ac1 = make_float4(0.f,0.f,0.f,0.f);
        float4 ac2 = make_float4(0.f,0.f,0.f,0.f);
        float4 ac3 = make_float4(0.f,0.f,0.f,0.f);
        int korder[3] = {k, kp, kn};
        #pragma unroll
        for (int seg = 0; seg < 3; seg++) {
            int kk = korder[seg];
            const float4* vp = (q < 2)
                ? reinterpret_cast<const float4*>(&sm->v_t[g][kk][0][4*q])
                : reinterpret_cast<const float4*>(&sm->ve[kk][0][4*(q-2)]);
            const float* sb0 = &sm->s[g][i0][seg*28];
            const float* sb1 = &sm->s[g][i1][seg*28];
            const float* sb2 = &sm->s[g][i2][seg*28];
            const float* sb3 = &sm->s[g][i3][seg*28];
            #pragma unroll
            for (int j4 = 0; j4 < 6; j4++) {
                float4 s0 = *reinterpret_cast<const float4*>(&sb0[4*j4]);
                float4 s1 = *reinterpret_cast<const float4*>(&sb1[4*j4]);
                float4 s2 = *reinterpret_cast<const float4*>(&sb2[4*j4]);
                float4 s3 = *reinterpret_cast<const float4*>(&sb3[4*j4]);
                const float sa0[4] = {s0.x, s0.y, s0.z, s0.w};
                const float sa1[4] = {s1.x, s1.y, s1.z, s1.w};
                const float sa2[4] = {s2.x, s2.y, s2.z, s2.w};
                const float sa3[4] = {s3.x, s3.y, s3.z, s3.w};
                #pragma unroll
                for (int e = 0; e < 4; e++) {
                    float4 v = vp[2*(4*j4 + e)];
                    float a0 = sa0[e];
                    ac0.x += a0*v.x; ac0.y += a0*v.y; ac0.z += a0*v.z; ac0.w += a0*v.w;
                    float a1 = sa1[e];
                    ac1.x += a1*v.x; ac1.y += a1*v.y; ac1.z += a1*v.z; ac1.w += a1*v.w;
                    float a2 = sa2[e];
                    ac2.x += a2*v.x; ac2.y += a2*v.y; ac2.z += a2*v.z; ac2.w += a2*v.w;
                    float a3 = sa3[e];
                    ac3.x += a3*v.x; ac3.y += a3*v.y; ac3.z += a3*v.z; ac3.w += a3*v.w;
                }
            }
            {   // tail j = 24
                float4 v = vp[48];
                float a0 = sb0[24];
                ac0.x += a0*v.x; ac0.y += a0*v.y; ac0.z += a0*v.z; ac0.w += a0*v.w;
                float a1 = sb1[24];
                ac1.x += a1*v.x; ac1.y += a1*v.y; ac1.z += a1*v.z; ac1.w += a1*v.w;
                float a2 = sb2[24];
                ac2.x += a2*v.x; ac2.y += a2*v.y; ac2.z += a2*v.z; ac2.w += a2*v.w;
                float a3 = sb3[24];
                ac3.x += a3*v.x; ac3.y += a3*v.y; ac3.z += a3*v.z; ac3.w += a3*v.w;
            }
        }
        if (q >= 2) {
            ac0.x *= 0.1f; ac0.y *= 0.1f; ac0.z *= 0.1f; ac0.w *= 0.1f;
            ac1.x *= 0.1f; ac1.y *= 0.1f; ac1.z *= 0.1f; ac1.w *= 0.1f;
            ac2.x *= 0.1f; ac2.y *= 0.1f; ac2.z *= 0.1f; ac2.w *= 0.1f;
            ac3.x *= 0.1f; ac3.y *= 0.1f; ac3.z *= 0.1f; ac3.w *= 0.1f;
        }
        int base_out = b*38400 + g*4800 + h2*1200 + k*400 + 4*q;
        *reinterpret_cast<float4*>(&g_ret1[base_out + i0*16]) = ac0;
        *reinterpret_cast<float4*>(&g_ret1[base_out + i1*16]) = ac1;
        *reinterpret_cast<float4*>(&g_ret1[base_out + i2*16]) = ac2;
        if (has3)
            *reinterpret_cast<float4*>(&g_ret1[base_out + i3*16]) = ac3;

        // squared partials into sq[g][16*i + 4q .. +3]
        float4 q0 = make_float4(ac0.x*ac0.x, ac0.y*ac0.y, ac0.z*ac0.z, ac0.w*ac0.w);
        float4 q1 = make_float4(ac1.x*ac1.x, ac1.y*ac1.y, ac1.z*ac1.z, ac1.w*ac1.w);
        float4 q2 = make_float4(ac2.x*ac2.x, ac2.y*ac2.y, ac2.z*ac2.z, ac2.w*ac2.w);
        int sbase = g*400 + 4*q;
        *reinterpret_cast<float4*>(&sq[sbase + i0*16]) = q0;
        *reinterpret_cast<float4*>(&sq[sbase + i1*16]) = q1;
        *reinterpret_cast<float4*>(&sq[sbase + i2*16]) = q2;
        if (has3) {
            float4 q3 = make_float4(ac3.x*ac3.x, ac3.y*ac3.y, ac3.z*ac3.z, ac3.w*ac3.w);
            *reinterpret_cast<float4*>(&sq[sbase + i3*16]) = q3;
        }
    }
    __syncthreads();

    // ---- reduce over g: 400 (i,e) partials -> g_pp, deterministic ----
    if (tid < 400) {
        float s = 0.f;
        #pragma unroll
        for (int g = 0; g < 8; g++) s += sq[g*400 + tid];
        g_pp[(b*4 + h2)*1200 + k*400 + tid] = s;
    }
}

// -------------------- kernel 3: norms + undo-gather + hash softmax + store ------
__global__ __launch_bounds__(512)
void k_fin(float* __restrict__ out)
{
    __shared__ float rd[300];
    __shared__ float bsn[224];
    __shared__ int   u[224];
    __shared__ float prob[4][28];
    int b = blockIdx.x, th = blockIdx.y;
    int n = b / WAX, w = b % WAX;
    int tid = threadIdx.x;
    const float* rb = &g_ret1[b*38400];
    const int t0 = th*28;

    if (tid < 300) {
        const float* pp = &g_pp[b*4800];
        float s = 0.f;
        #pragma unroll
        for (int h2 = 0; h2 < 4; h2++) {
            #pragma unroll
            for (int kk2 = 0; kk2 < 3; kk2++) {
                int base = (h2*3 + kk2)*400;
                int x0 = tid + 300 - 100*kk2;
                if (x0 >= 300) x0 -= 300;
                s += pp[base + x0];
                if (x0 < 100) s += pp[base + x0 + 300];
            }
        }
        rd[tid] = 1.0f / fmaxf(sqrtf(s), EPS_N);
    }
    if (tid >= 288) {
        int p = tid - 288;
        int h2 = p / 56, t = p % 56;
        float sv = 0.f, sq2 = 0.f;
        #pragma unroll
        for (int g = 0; g < 8; g++) {
            float v = g_bsg[((b*8 + g)*4 + h2)*75 + t];
            sv += v; sq2 += v*v;
        }
        bsn[p] = sv / fmaxf(sqrtf(sq2), EPS_N);
        u[p] = g_undo[b*224 + p];
    }
    __syncthreads();

    if (tid < 28) {
        int t = t0 + tid;
        float bv[4]; float m = -1e30f;
        #pragma unroll
        for (int h = 0; h < 4; h++) { bv[h] = bsn[u[h*56 + t]]; m = fmaxf(m, bv[h]); }
        float sum = 0.f;
        #pragma unroll
        for (int h = 0; h < 4; h++) { float e = __expf(bv[h] - m); prob[h][tid] = e; sum += e; }
        float rs = 1.0f / sum;
        #pragma unroll
        for (int h = 0; h < 4; h++) prob[h][tid] *= rs;
    }
    __syncthreads();

    for (int o = tid; o < 28*32; o += 512) {
        int tl = o >> 5, e2 = o & 31;
        int t  = t0 + tl;
        float acc0 = 0.f, acc1 = 0.f;
        #pragma unroll
        for (int h = 0; h < 4; h++) {
            int p  = u[h*56 + t];
            int h4 = p / 56, t2 = p % 56, k4 = t2 / 25, i4 = t2 % 25;
            int f0 = h4*9600 + k4*3200 + i4*128 + 4*e2;
            float4 rv = *reinterpret_cast<const float4*>(&rb[f0]);
            int m0 = (200*k4 + 128*i4 + 4*e2) % 300;
            int m2 = m0 + 2; if (m2 >= 300) m2 -= 300;
            float ph = prob[h][tl];
            acc0 += (rv.x*rd[m0] + rv.y*rd[m0+1]) * ph;
            acc1 += (rv.z*rd[m2] + rv.w*rd[m2+1]) * ph;
        }
        int e = 2*e2;
        out[((n*OUTC + e    )*HAX + t)*WAX + w] = acc0;
        out[((n*OUTC + e + 1)*HAX + t)*WAX + w] = acc1;
    }
}

// -------------------- launch --------------------
extern "C" void kernel_launch(void* const* d_in, const int* in_sizes, int n_in,
                              void* d_out, int out_size)
{
    const float* x     = (const float*)d_in[0];
    const float* cw    = (const float*)d_in[1];
    const float* gamma = (const float*)d_in[2];
    const float* beta  = (const float*)d_in[3];
    const float* rel   = (const float*)d_in[4];
    const float* rot   = (const float*)d_in[5];
    float* out = (float*)d_out;

    cudaFuncSetAttribute(k_attn, cudaFuncAttributeMaxDynamicSharedMemorySize,
                         (int)sizeof(SmemAtt));

    k_conv<<<dim3(BATCH, 4), 256>>>(x, cw, gamma, beta);
    k_code<<<BATCH, 224>>>(rot);
    k_attn<<<dim3(BATCH, 4, 3), 512, sizeof(SmemAtt)>>>(rel);
    k_fin <<<dim3(BATCH, 2), 512>>>(out);
}